// round 14
// baseline (speedup 1.0000x reference)
#include <cuda.h>
#include <cuda_runtime.h>
#include <cuda_bf16.h>
#include <cuda_fp16.h>
#include <math.h>
#include <stdint.h>

#define B_    64
#define L_    1024
#define N_    64
#define INSZ  128
#define MEM   1024
#define DEC   3

#define NCTA  64
#define NT    512
#define JB    16

// ---------------- scratch ----------------------------------------------------
__device__ __half g_ih  [(size_t)L_ * 2 * B_ * INSZ];         // [l][part hi/lo][b][k]
__device__ uint2  g_wfrag[24 * 16 * 512];                     // W_im fragments (1.5MB)
__device__ float g_proj [(size_t)L_ * 3 * MEM * B_];          // [l][col][b]
__device__ __half g_hA  [2 * 64 * MEM];                       // double-buffered h fp16 [buf][b][j]
__device__ float g_mem  [(size_t)L_ * MEM * B_];              // [l][j][b]
__device__ unsigned int g_grp[8 * 64];                        // per-group monotonic counters

// ---------------- PTX helpers ------------------------------------------------
__device__ __forceinline__ uint32_t smem_u32(const void* p) {
    uint32_t a;
    asm("{ .reg .u64 t; cvta.to.shared.u64 t, %1; cvt.u32.u64 %0, t; }" : "=r"(a) : "l"(p));
    return a;
}
#define SWZ(o) ((o) ^ (((o) >> 3) & 0x70))

#define MBAR_INIT(a, c) asm volatile("mbarrier.init.shared.b64 [%0], %1;" :: "r"((uint32_t)(a)), "r"((uint32_t)(c)) : "memory")
#define MBAR_EXPECT_TX(a, n) asm volatile("mbarrier.arrive.expect_tx.shared.b64 _, [%0], %1;" :: "r"((uint32_t)(a)), "r"((uint32_t)(n)) : "memory")

#define MBAR_WAIT(a, par) do { \
    uint32_t _m = (uint32_t)(a); uint32_t _p = (uint32_t)(par); uint32_t _d; \
    asm volatile("{\n\t.reg .pred p;\n\t" \
        "mbarrier.try_wait.parity.acquire.cta.shared::cta.b64 p, [%1], %2;\n\t" \
        "selp.b32 %0, 1, 0, p;\n\t}" : "=r"(_d) : "r"(_m), "r"(_p) : "memory"); \
    if (!_d) { \
        asm volatile("{\n\t.reg .pred P1;\n\tWL_%=:\n\t" \
            "mbarrier.try_wait.parity.acquire.cta.shared::cta.b64 P1, [%0], %1, 0x989680;\n\t" \
            "@P1 bra.uni WD_%=;\n\tbra.uni WL_%=;\n\tWD_%=:\n\t}" \
            :: "r"(_m), "r"(_p) : "memory"); \
    } } while (0)

#define TMA_LD(dst, tm, cx, cy, cz, mbar) \
    asm volatile("cp.async.bulk.tensor.3d.shared::cta.global.tile.mbarrier::complete_tx::bytes " \
        "[%0], [%1, {%2, %3, %4}], [%5];" \
        :: "r"((uint32_t)(dst)), "l"(tm), "r"((int32_t)(cx)), "r"((int32_t)(cy)), "r"((int32_t)(cz)), \
           "r"((uint32_t)(mbar)) : "memory")

#define FENCE_ASYNC_ALL() asm volatile("fence.proxy.async;" ::: "memory")
#define BAR_ARRIVE(id, cnt) asm volatile("bar.arrive %0, %1;" :: "r"(id), "r"(cnt) : "memory")
#define BAR_SYNC(id, cnt)   asm volatile("bar.sync %0, %1;"   :: "r"(id), "r"(cnt) : "memory")

__device__ __forceinline__ void ldmatrix4(uint32_t& a0, uint32_t& a1, uint32_t& a2, uint32_t& a3,
                                          uint32_t addr) {
    asm volatile("ldmatrix.sync.aligned.m8n8.x4.shared.b16 {%0,%1,%2,%3}, [%4];"
        : "=r"(a0), "=r"(a1), "=r"(a2), "=r"(a3) : "r"(addr));
}
__device__ __forceinline__ void mma16816h(float* d, uint32_t a0, uint32_t a1, uint32_t a2, uint32_t a3,
                                          uint32_t b0, uint32_t b1) {
    asm volatile("mma.sync.aligned.m16n8k16.row.col.f32.f16.f16.f32 "
        "{%0,%1,%2,%3}, {%4,%5,%6,%7}, {%8,%9}, {%0,%1,%2,%3};"
        : "+f"(d[0]), "+f"(d[1]), "+f"(d[2]), "+f"(d[3])
        : "r"(a0), "r"(a1), "r"(a2), "r"(a3), "r"(b0), "r"(b1));
}

__device__ __forceinline__ float tanh_acc(float x) {
    float ax = fabsf(x);
    float e  = __expf(-2.0f * ax);
    float t  = (1.0f - e) / (1.0f + e);
    return copysignf(t, x);
}
__device__ __forceinline__ float sigmoid_acc(float z) {
    return 1.0f / (1.0f + __expf(-z));
}
__device__ __forceinline__ uint32_t packh(float x, float y, bool lo) {
    __half xh = __float2half(x), yh = __float2half(y);
    if (lo) {
        xh = __float2half(x - __half2float(xh));
        yh = __float2half(y - __half2float(yh));
    }
    return ((uint32_t)__half_as_ushort(yh) << 16) | (uint32_t)__half_as_ushort(xh);
}

__global__ void reset_kernel() {
    int t = threadIdx.x;
    if (t < 512) g_grp[t] = 0u;
}

// ---------------- K1a: sense (8 tokens/block) -> fp16 hi/lo -----------------------
__global__ void __launch_bounds__(128) sense_kernel(const float* __restrict__ x,
                                                    const float* __restrict__ Ws,
                                                    const float* __restrict__ bs) {
    __shared__ float xs[8][N_];
    int t = threadIdx.x;
    int bl0 = blockIdx.x * 8;
#pragma unroll
    for (int i = 0; i < 4; i++) {
        int idx = t + i * 128;
        xs[idx >> 6][idx & 63] = x[(size_t)bl0 * N_ + idx];
    }
    __syncthreads();
    float acc[8];
    float bias = bs[t];
#pragma unroll
    for (int i = 0; i < 8; i++) acc[i] = bias;
    for (int n = 0; n < N_; n++) {
        float w = Ws[n * INSZ + t];
#pragma unroll
        for (int i = 0; i < 8; i++) acc[i] += xs[i][n] * w;
    }
#pragma unroll
    for (int i = 0; i < 8; i++) {
        int bl = bl0 + i;
        int b = bl >> 10, l = bl & (L_ - 1);
        __half hh = __float2half(acc[i]);
        __half hl = __float2half(acc[i] - __half2float(hh));
        g_ih[(((size_t)l * 2 + 0) * B_ + b) * INSZ + t] = hh;
        g_ih[(((size_t)l * 2 + 1) * B_ + b) * INSZ + t] = hl;
    }
}

// ---------------- K1b-pre: W_im fragments -----------------------------------------
__global__ void __launch_bounds__(256) wprep_kernel(const float* __restrict__ Wim) {
    int ntile = blockIdx.x;
    int t = threadIdx.x;
    for (int q = t; q < 16 * 16 * 32; q += 256) {
        int lane = q & 31, n8 = (q >> 5) & 15, wsel = q >> 9;
        bool lo = wsel >= 8;
        int n = ntile * 128 + n8 * 8 + (lane >> 2);
        int k0 = (wsel & 7) * 16 + (lane & 3) * 2;
        const float* wp = Wim + (size_t)k0 * 3072 + n;
        g_wfrag[(size_t)ntile * 8192 + q] =
            make_uint2(packh(wp[0], wp[3072], lo),
                       packh(wp[8 * 3072], wp[9 * 3072], lo));
    }
}

// ---------------- K1b: proj via mma.sync (unchanged) -------------------------------
#define PSM_WF 0
#define PSM_A  65536
#define PSM_ST 98304
#define PSM_TOT (98304 + 128 * 65 * 4)
__global__ void __launch_bounds__(128) proj_tc() {
    extern __shared__ char sm[];
    uint32_t sb = smem_u32(sm);
    const uint2* Wfs = (const uint2*)(sm + PSM_WF);
    float* St = (float*)(sm + PSM_ST);
    int ntile = blockIdx.x;
    int l0 = blockIdx.y * 4;
    int t = threadIdx.x, w = t >> 5, lane = t & 31;
    int mbase = (w & 1) * 2;
    int nbase = (w >> 1) * 8;

    {
        const uint4* wsrc = (const uint4*)(g_wfrag + (size_t)ntile * 8192);
#pragma unroll
        for (int i = 0; i < 32; i++)
            ((uint4*)(sm + PSM_WF))[t + i * 128] = wsrc[t + i * 128];
    }
    __syncthreads();

    for (int li = 0; li < 4; li++) {
        int l = l0 + li;
        const uint4* asrc = (const uint4*)(g_ih + (size_t)l * 2 * B_ * INSZ);
#pragma unroll
        for (int i = 0; i < 16; i++) {
            int q = t + i * 128;
            int part = q >> 10;
            int rb = (q >> 4) & 63;
            int k0 = (q & 15) * 8;
            uint32_t dst = (uint32_t)(PSM_A + part * 16384 + (k0 >> 6) * 8192)
                         + SWZ((uint32_t)(rb * 128 + (k0 & 63) * 2));
            *(uint4*)(sm + dst) = asrc[q];
        }
        __syncthreads();

        float acc[2][8][4];
#pragma unroll
        for (int a = 0; a < 2; a++)
#pragma unroll
            for (int b2 = 0; b2 < 8; b2++)
#pragma unroll
                for (int c = 0; c < 4; c++) acc[a][b2][c] = 0.0f;

#pragma unroll
        for (int gk = 0; gk < 24; gk++) {
            int part = (gk >= 8 && gk < 16) ? 1 : 0;
            int wsel = (gk < 8) ? gk : gk - 8;
            int kk = gk & 7;
            uint32_t a0[2], a1[2], a2[2], a3[2];
#pragma unroll
            for (int mt = 0; mt < 2; mt++) {
                uint32_t addr = sb + (uint32_t)(PSM_A + part * 16384 + (kk >> 2) * 8192)
                    + SWZ((uint32_t)(((mbase + mt) * 16 + (lane & 15)) * 128
                                     + ((lane >> 4) << 4) + (kk & 3) * 32));
                ldmatrix4(a0[mt], a1[mt], a2[mt], a3[mt], addr);
            }
#pragma unroll
            for (int nn = 0; nn < 8; nn++) {
                uint2 bv = Wfs[(size_t)(wsel * 16 + nbase + nn) * 32 + lane];
#pragma unroll
                for (int mt = 0; mt < 2; mt++)
                    mma16816h(acc[mt][nn], a0[mt], a1[mt], a2[mt], a3[mt], bv.x, bv.y);
            }
        }
        __syncthreads();

        {
            int c0 = (lane & 3) * 2;
#pragma unroll
            for (int mt = 0; mt < 2; mt++) {
                int r0 = (mbase + mt) * 16 + (lane >> 2);
#pragma unroll
                for (int nn = 0; nn < 8; nn++) {
                    int col = (nbase + nn) * 8 + c0;
                    St[col * 65 + r0]           = acc[mt][nn][0];
                    St[(col + 1) * 65 + r0]     = acc[mt][nn][1];
                    St[col * 65 + r0 + 8]       = acc[mt][nn][2];
                    St[(col + 1) * 65 + r0 + 8] = acc[mt][nn][3];
                }
            }
        }
        __syncthreads();

        {
            float* dst = g_proj + (size_t)l * 3072 * 64 + (size_t)ntile * 128 * 64;
#pragma unroll
            for (int i = 0; i < 64; i++) {
                int q = t + i * 128;
                dst[q] = St[(q >> 6) * 65 + (q & 63)];
            }
        }
        __syncthreads();
    }
}

// ---------------- K2: scan (64 CTAs, JB=16, single fp16 W in smem) ------------------
// Group g = blockIdx.x>>3 owns A chunk g (8 CTAs each). 16 warps: kg = wid>>1 (K=128
// chunk), mg = wid&1 (32 of 64 rows). N = 32 cols = [a(16) | c(16)]. FULL[kg] single
// completion per step (parity l&1); per-group monotonic counters; h double-buffered.
#define OFF_FULL   0       // 8 x 8B
#define OFF_W      1024    // 64 gk x 4 n8 x 32 lanes x 8B = 64KB
#define OFF_SLOTS  66560   // 8 x 16384 = 128KB
#define OFF_RED    197632  // 4 x 64 x 33 x 4 = 33792
#define SMEM_SCAN  (197632 + 4 * 64 * 33 * 4)

__global__ void __launch_bounds__(NT, 1)
scan_tc(const float* __restrict__ Wmm, const __grid_constant__ CUtensorMap tmap) {
    extern __shared__ char smem[];
    uint32_t sb = smem_u32(smem);
    float* RED = (float*)(smem + OFF_RED);
    uint2* Wf  = (uint2*)(smem + OFF_W);
    int t = threadIdx.x, wid = t >> 5, lane = t & 31;
    int kg = wid >> 1, mg = wid & 1;
    int j0 = blockIdx.x * JB;
    int mygrp = blockIdx.x >> 3;

    if (t == 0) {
#pragma unroll
        for (int c = 0; c < 8; c++) MBAR_INIT(sb + OFF_FULL + c * 8, 1);
    }

    // W fragments (fp16, hi only) in smem: [gk 64][n8 4][lane 32]
    // n_local = n8*8 + lane>>2 in 0..31: 0-15 -> a cols j0+n, 16-31 -> c cols MEM+j0+n-16
    for (int idx = t; idx < 64 * 4 * 32; idx += NT) {
        int ln = idx & 31, n8 = (idx >> 5) & 3, gk = idx >> 7;
        int n_local = n8 * 8 + (ln >> 2);
        int col = (n_local < 16) ? (j0 + n_local) : (MEM + j0 + n_local - 16);
        int k0 = gk * 16 + (ln & 3) * 2;
        const float* wp = Wmm + (size_t)k0 * 2048;
        Wf[idx] = make_uint2(packh(wp[col], wp[2048 + col], false),
                             packh(wp[8 * 2048 + col], wp[9 * 2048 + col], false));
    }

    // init h = 0 into buffer 0 (own 16 columns)
#pragma unroll
    for (int p = 0; p < 2; p++) {
        int idx = t + p * NT;
        int b = idx >> 4, jj = idx & 15;
        g_hA[b * MEM + j0 + jj] = __float2half(0.0f);
    }
    float hreg[2] = {0.0f, 0.0f};
    __syncthreads();
    if (t == 0) {
        __threadfence();
        atomicAdd(&g_grp[mygrp * 64], 1u);
    }

    int q = kg & 3;
    int redbar = 4 + q;
    uint32_t myfull = sb + OFF_FULL + kg * 8;
    uint32_t myslot = sb + OFF_SLOTS + (uint32_t)kg * 16384u;
    int lbase = (lane & 15) * 128 + ((lane >> 4) << 4);
    volatile unsigned int* mycnt = (volatile unsigned int*)&g_grp[kg * 64];

    for (int l = 0; l < L_; l++) {
        int par = l & 1;
        size_t pb = (size_t)l * 3072 * 64;
        float ia[2], ic[2], io[2];
#pragma unroll
        for (int p = 0; p < 2; p++) {
            int idx = t + p * NT;
            int b = idx >> 4, j = j0 + (idx & 15);
            ia[p] = __ldg(&g_proj[pb + (size_t)j * 64 + b]);
            ic[p] = __ldg(&g_proj[pb + (size_t)(MEM + j) * 64 + b]);
            io[p] = __ldg(&g_proj[pb + (size_t)(2 * MEM + j) * 64 + b]);
        }

        // JIT producer: mg0-lane0 of each kg polls its source group, issues its chunk
        if (mg == 0 && lane == 0) {
            unsigned int tgt = 8u * (unsigned int)(l + 1);
            while (*mycnt < tgt) { }
            __threadfence();
            FENCE_ASYNC_ALL();
            MBAR_EXPECT_TX(myfull, 16384);
            TMA_LD(myslot,        &tmap, kg * 128,      par * 64, 0, myfull);
            TMA_LD(myslot + 8192, &tmap, kg * 128 + 64, par * 64, 0, myfull);
        }

        float acc[2][4][4];
#pragma unroll
        for (int a = 0; a < 2; a++)
#pragma unroll
            for (int b2 = 0; b2 < 4; b2++)
#pragma unroll
                for (int c = 0; c < 4; c++) acc[a][b2][c] = 0.0f;

        MBAR_WAIT(myfull, par);

#pragma unroll
        for (int kk = 0; kk < 8; kk++) {
            const uint2* wp = Wf + (size_t)((kg * 8 + kk) * 4) * 32 + lane;
            uint2 bv0 = wp[0];
            uint2 bv1 = wp[32];
            uint2 bv2 = wp[64];
            uint2 bv3 = wp[96];
            uint32_t kbase = myslot + (uint32_t)((kk >> 2) * 8192);
            uint32_t loff  = (uint32_t)SWZ(lbase + (kk & 3) * 32);
#pragma unroll
            for (int mt = 0; mt < 2; mt++) {
                uint32_t addr = kbase + (uint32_t)((mg * 2 + mt) * 2048) + loff;
                uint32_t a0, a1, a2, a3;
                ldmatrix4(a0, a1, a2, a3, addr);
                mma16816h(acc[mt][0], a0, a1, a2, a3, bv0.x, bv0.y);
                mma16816h(acc[mt][1], a0, a1, a2, a3, bv1.x, bv1.y);
                mma16816h(acc[mt][2], a0, a1, a2, a3, bv2.x, bv2.y);
                mma16816h(acc[mt][3], a0, a1, a2, a3, bv3.x, bv3.y);
            }
        }

        // RED: kg<4 write buffer q, kg>=4 accumulate (named barrier per q)
        {
            float* rp = RED + (size_t)q * (64 * 33);
            int r0 = mg * 32 + (lane >> 2);
            int c0 = (lane & 3) * 2;
            if (kg < 4) {
#pragma unroll
                for (int mt = 0; mt < 2; mt++)
#pragma unroll
                    for (int np = 0; np < 4; np++) {
                        float* qp = rp + (r0 + mt * 16) * 33 + np * 8 + c0;
                        qp[0]          = acc[mt][np][0];
                        qp[1]          = acc[mt][np][1];
                        qp[8 * 33]     = acc[mt][np][2];
                        qp[8 * 33 + 1] = acc[mt][np][3];
                    }
                BAR_ARRIVE(redbar, 128);
            } else {
                BAR_SYNC(redbar, 128);
#pragma unroll
                for (int mt = 0; mt < 2; mt++)
#pragma unroll
                    for (int np = 0; np < 4; np++) {
                        float* qp = rp + (r0 + mt * 16) * 33 + np * 8 + c0;
                        qp[0]          += acc[mt][np][0];
                        qp[1]          += acc[mt][np][1];
                        qp[8 * 33]     += acc[mt][np][2];
                        qp[8 * 33 + 1] += acc[mt][np][3];
                    }
            }
        }
        __syncthreads();

        // combine + nBRC update (2 states per thread); write h to buffer (l+1)&1
#pragma unroll
        for (int p = 0; p < 2; p++) {
            int idx = t + p * NT;
            int b = idx >> 4, jj = idx & 15, j = j0 + jj;
            float ma = 0.0f, mc = 0.0f;
#pragma unroll
            for (int qq = 0; qq < 4; qq++) {
                const float* rq = RED + (size_t)qq * (64 * 33);
                ma += rq[b * 33 + jj];
                mc += rq[b * 33 + 16 + jj];
            }
            float a  = 1.0f + tanh_acc(ia[p] + ma);
            float cg = sigmoid_acc(ic[p] + mc);
            float hn = cg * hreg[p] + (1.0f - cg) * tanh_acc(io[p] + a * hreg[p]);
            hreg[p] = hn;
            g_hA[(((l + 1) & 1) * 64 + b) * MEM + j] = __float2half(hn);
            g_mem[(size_t)l * (MEM * B_) + (size_t)j * B_ + b] = hn;
        }
        __syncthreads();

        if (t == 0) {
            __threadfence();
            atomicAdd(&g_grp[mygrp * 64], 1u);
        }
    }
}

// ---------------- K3: logits + softmax (4 timesteps/block) --------------------------
__global__ void __launch_bounds__(256) logits_kernel(const float* __restrict__ Wact,
                                                     const float* __restrict__ bact,
                                                     float* __restrict__ out) {
    __shared__ float Wa[MEM * DEC];
    int t = threadIdx.x;
    int l = blockIdx.x * 4 + (t >> 6);
    int b = t & 63;
    for (int idx = t; idx < MEM * DEC; idx += 256) Wa[idx] = Wact[idx];
    __syncthreads();

    float a0 = bact[0], a1 = bact[1], a2 = bact[2];
    const float* mp = g_mem + (size_t)l * MEM * B_ + b;
#pragma unroll 8
    for (int k = 0; k < MEM; k++) {
        float v = mp[(size_t)k * B_];
        a0 += v * Wa[k * 3 + 0];
        a1 += v * Wa[k * 3 + 1];
        a2 += v * Wa[k * 3 + 2];
    }
    float m  = fmaxf(a0, fmaxf(a1, a2));
    float e0 = __expf(a0 - m), e1 = __expf(a1 - m), e2 = __expf(a2 - m);
    float inv = 1.0f / (e0 + e1 + e2);
    size_t ob = ((size_t)b * L_ + l) * DEC;
    out[ob + 0] = e0 * inv;
    out[ob + 1] = e1 * inv;
    out[ob + 2] = e2 * inv;
}

// ---------------- launch --------------------------------------------------------------
typedef CUresult (*PFN_tmapEncode)(
    CUtensorMap*, CUtensorMapDataType, cuuint32_t, void*,
    const cuuint64_t*, const cuuint64_t*, const cuuint32_t*, const cuuint32_t*,
    CUtensorMapInterleave, CUtensorMapSwizzle, CUtensorMapL2promotion,
    CUtensorMapFloatOOBfill);

extern "C" void kernel_launch(void* const* d_in, const int* in_sizes, int n_in,
                              void* d_out, int out_size) {
    (void)in_sizes; (void)n_in; (void)out_size;
    const float* x   = (const float*)d_in[0];
    const float* Ws  = (const float*)d_in[1];
    const float* bs  = (const float*)d_in[2];
    const float* Wim = (const float*)d_in[3];
    const float* Wmm = (const float*)d_in[4];
    const float* Wac = (const float*)d_in[5];
    const float* bac = (const float*)d_in[6];
    float* out = (float*)d_out;

    void* hs_ptr = nullptr;
    cudaGetSymbolAddress(&hs_ptr, g_hA);
    PFN_tmapEncode enc = nullptr;
    cudaDriverEntryPointQueryResult qr;
    cudaGetDriverEntryPoint("cuTensorMapEncodeTiled", (void**)&enc,
                            cudaEnableDefault, &qr);
    CUtensorMap tmap;
    {
        cuuint64_t dims[3]    = {MEM, 128, 1};
        cuuint64_t strides[2] = {MEM * 2, (cuuint64_t)MEM * 2 * 128};
        cuuint32_t box[3]     = {64, 64, 1};
        cuuint32_t es[3]      = {1, 1, 1};
        enc(&tmap, CU_TENSOR_MAP_DATA_TYPE_FLOAT16, 3, hs_ptr,
            dims, strides, box, es,
            CU_TENSOR_MAP_INTERLEAVE_NONE, CU_TENSOR_MAP_SWIZZLE_128B,
            CU_TENSOR_MAP_L2_PROMOTION_L2_128B, CU_TENSOR_MAP_FLOAT_OOB_FILL_NONE);
    }

    cudaFuncSetAttribute(proj_tc,  cudaFuncAttributeMaxDynamicSharedMemorySize, PSM_TOT);
    cudaFuncSetAttribute(scan_tc,  cudaFuncAttributeMaxDynamicSharedMemorySize, SMEM_SCAN);

    reset_kernel<<<1, 512>>>();
    sense_kernel<<<B_ * L_ / 8, 128>>>(x, Ws, bs);
    wprep_kernel<<<24, 256>>>(Wim);
    proj_tc<<<dim3(24, 256), 128, PSM_TOT>>>();
    scan_tc<<<NCTA, NT, SMEM_SCAN>>>(Wmm, tmap);
    logits_kernel<<<L_ / 4, 256>>>(Wac, bac, out);
}

// round 15
// speedup vs baseline: 1.3589x; 1.3589x over previous
#include <cuda.h>
#include <cuda_runtime.h>
#include <cuda_bf16.h>
#include <cuda_fp16.h>
#include <math.h>
#include <stdint.h>

#define B_    64
#define L_    1024
#define N_    64
#define INSZ  128
#define MEM   1024
#define DEC   3

#define NCTA  128
#define NT    512
#define JB    8

// ---------------- scratch ----------------------------------------------------
__device__ __half g_ih  [(size_t)L_ * 2 * B_ * INSZ];         // [l][part hi/lo][b][k]
__device__ uint2  g_wfrag[24 * 16 * 512];                     // W_im fragments (1.5MB)
__device__ float g_proj [(size_t)L_ * 3 * MEM * B_];          // [l][col][b]
__device__ __half g_hA  [2 * 64 * MEM];                       // double-buffered h fp16
__device__ float g_mem  [(size_t)L_ * MEM * B_];              // [l][j][b]
__device__ unsigned int g_grp[8 * 64];                        // per-group monotonic counters

// ---------------- PTX helpers ------------------------------------------------
__device__ __forceinline__ uint32_t smem_u32(const void* p) {
    uint32_t a;
    asm("{ .reg .u64 t; cvta.to.shared.u64 t, %1; cvt.u32.u64 %0, t; }" : "=r"(a) : "l"(p));
    return a;
}
#define SWZ(o) ((o) ^ (((o) >> 3) & 0x70))

#define MBAR_INIT(a, c) asm volatile("mbarrier.init.shared.b64 [%0], %1;" :: "r"((uint32_t)(a)), "r"((uint32_t)(c)) : "memory")
#define MBAR_EXPECT_TX(a, n) asm volatile("mbarrier.arrive.expect_tx.shared.b64 _, [%0], %1;" :: "r"((uint32_t)(a)), "r"((uint32_t)(n)) : "memory")

#define MBAR_WAIT(a, par) do { \
    uint32_t _m = (uint32_t)(a); uint32_t _p = (uint32_t)(par); uint32_t _d; \
    asm volatile("{\n\t.reg .pred p;\n\t" \
        "mbarrier.try_wait.parity.acquire.cta.shared::cta.b64 p, [%1], %2;\n\t" \
        "selp.b32 %0, 1, 0, p;\n\t}" : "=r"(_d) : "r"(_m), "r"(_p) : "memory"); \
    if (!_d) { \
        asm volatile("{\n\t.reg .pred P1;\n\tWL_%=:\n\t" \
            "mbarrier.try_wait.parity.acquire.cta.shared::cta.b64 P1, [%0], %1, 0x989680;\n\t" \
            "@P1 bra.uni WD_%=;\n\tbra.uni WL_%=;\n\tWD_%=:\n\t}" \
            :: "r"(_m), "r"(_p) : "memory"); \
    } } while (0)

#define TMA_LD(dst, tm, cx, cy, cz, mbar) \
    asm volatile("cp.async.bulk.tensor.3d.shared::cta.global.tile.mbarrier::complete_tx::bytes " \
        "[%0], [%1, {%2, %3, %4}], [%5];" \
        :: "r"((uint32_t)(dst)), "l"(tm), "r"((int32_t)(cx)), "r"((int32_t)(cy)), "r"((int32_t)(cz)), \
           "r"((uint32_t)(mbar)) : "memory")

#define FENCE_ASYNC_ALL() asm volatile("fence.proxy.async;" ::: "memory")
#define BAR_ARRIVE(id, cnt) asm volatile("bar.arrive %0, %1;" :: "r"(id), "r"(cnt) : "memory")
#define BAR_SYNC(id, cnt)   asm volatile("bar.sync %0, %1;"   :: "r"(id), "r"(cnt) : "memory")

__device__ __forceinline__ void ldmatrix4(uint32_t& a0, uint32_t& a1, uint32_t& a2, uint32_t& a3,
                                          uint32_t addr) {
    asm volatile("ldmatrix.sync.aligned.m8n8.x4.shared.b16 {%0,%1,%2,%3}, [%4];"
        : "=r"(a0), "=r"(a1), "=r"(a2), "=r"(a3) : "r"(addr));
}
__device__ __forceinline__ void mma16816h(float* d, uint32_t a0, uint32_t a1, uint32_t a2, uint32_t a3,
                                          uint32_t b0, uint32_t b1) {
    asm volatile("mma.sync.aligned.m16n8k16.row.col.f32.f16.f16.f32 "
        "{%0,%1,%2,%3}, {%4,%5,%6,%7}, {%8,%9}, {%0,%1,%2,%3};"
        : "+f"(d[0]), "+f"(d[1]), "+f"(d[2]), "+f"(d[3])
        : "r"(a0), "r"(a1), "r"(a2), "r"(a3), "r"(b0), "r"(b1));
}

__device__ __forceinline__ float tanh_acc(float x) {
    float ax = fabsf(x);
    float e  = __expf(-2.0f * ax);
    float t  = (1.0f - e) / (1.0f + e);
    return copysignf(t, x);
}
__device__ __forceinline__ float sigmoid_acc(float z) {
    return 1.0f / (1.0f + __expf(-z));
}
__device__ __forceinline__ uint32_t packh(float x, float y, bool lo) {
    __half xh = __float2half(x), yh = __float2half(y);
    if (lo) {
        xh = __float2half(x - __half2float(xh));
        yh = __float2half(y - __half2float(yh));
    }
    return ((uint32_t)__half_as_ushort(yh) << 16) | (uint32_t)__half_as_ushort(xh);
}

__global__ void reset_kernel() {
    int t = threadIdx.x;
    if (t < 512) g_grp[t] = 0u;
}

// ---------------- K1a: sense (8 tokens/block) -> fp16 hi/lo -----------------------
__global__ void __launch_bounds__(128) sense_kernel(const float* __restrict__ x,
                                                    const float* __restrict__ Ws,
                                                    const float* __restrict__ bs) {
    __shared__ float xs[8][N_];
    int t = threadIdx.x;
    int bl0 = blockIdx.x * 8;
#pragma unroll
    for (int i = 0; i < 4; i++) {
        int idx = t + i * 128;
        xs[idx >> 6][idx & 63] = x[(size_t)bl0 * N_ + idx];
    }
    __syncthreads();
    float acc[8];
    float bias = bs[t];
#pragma unroll
    for (int i = 0; i < 8; i++) acc[i] = bias;
    for (int n = 0; n < N_; n++) {
        float w = Ws[n * INSZ + t];
#pragma unroll
        for (int i = 0; i < 8; i++) acc[i] += xs[i][n] * w;
    }
#pragma unroll
    for (int i = 0; i < 8; i++) {
        int bl = bl0 + i;
        int b = bl >> 10, l = bl & (L_ - 1);
        __half hh = __float2half(acc[i]);
        __half hl = __float2half(acc[i] - __half2float(hh));
        g_ih[(((size_t)l * 2 + 0) * B_ + b) * INSZ + t] = hh;
        g_ih[(((size_t)l * 2 + 1) * B_ + b) * INSZ + t] = hl;
    }
}

// ---------------- K1b-pre: W_im fragments -----------------------------------------
__global__ void __launch_bounds__(256) wprep_kernel(const float* __restrict__ Wim) {
    int ntile = blockIdx.x;
    int t = threadIdx.x;
    for (int q = t; q < 16 * 16 * 32; q += 256) {
        int lane = q & 31, n8 = (q >> 5) & 15, wsel = q >> 9;
        bool lo = wsel >= 8;
        int n = ntile * 128 + n8 * 8 + (lane >> 2);
        int k0 = (wsel & 7) * 16 + (lane & 3) * 2;
        const float* wp = Wim + (size_t)k0 * 3072 + n;
        g_wfrag[(size_t)ntile * 8192 + q] =
            make_uint2(packh(wp[0], wp[3072], lo),
                       packh(wp[8 * 3072], wp[9 * 3072], lo));
    }
}

// ---------------- K1b: proj via mma.sync (256 threads, better occupancy) ------------
#define PSM_WF 0
#define PSM_A  65536
#define PSM_ST 98304
#define PSM_TOT (98304 + 128 * 65 * 4)
__global__ void __launch_bounds__(256) proj_tc() {
    extern __shared__ char sm[];
    uint32_t sb = smem_u32(sm);
    const uint2* Wfs = (const uint2*)(sm + PSM_WF);
    float* St = (float*)(sm + PSM_ST);
    int ntile = blockIdx.x;
    int l0 = blockIdx.y * 4;
    int t = threadIdx.x, w = t >> 5, lane = t & 31;
    int mbase = (w & 1) * 2;     // 2 m-tiles of 16 rows
    int nbase = (w >> 1) * 4;    // 4 n8-frags of 16

    {
        const uint4* wsrc = (const uint4*)(g_wfrag + (size_t)ntile * 8192);
#pragma unroll
        for (int i = 0; i < 16; i++)
            ((uint4*)(sm + PSM_WF))[t + i * 256] = wsrc[t + i * 256];
    }
    __syncthreads();

    for (int li = 0; li < 4; li++) {
        int l = l0 + li;
        const uint4* asrc = (const uint4*)(g_ih + (size_t)l * 2 * B_ * INSZ);
#pragma unroll
        for (int i = 0; i < 8; i++) {
            int q = t + i * 256;
            int part = q >> 10;
            int rb = (q >> 4) & 63;
            int k0 = (q & 15) * 8;
            uint32_t dst = (uint32_t)(PSM_A + part * 16384 + (k0 >> 6) * 8192)
                         + SWZ((uint32_t)(rb * 128 + (k0 & 63) * 2));
            *(uint4*)(sm + dst) = asrc[q];
        }
        __syncthreads();

        float acc[2][4][4];
#pragma unroll
        for (int a = 0; a < 2; a++)
#pragma unroll
            for (int b2 = 0; b2 < 4; b2++)
#pragma unroll
                for (int c = 0; c < 4; c++) acc[a][b2][c] = 0.0f;

#pragma unroll
        for (int gk = 0; gk < 24; gk++) {
            int part = (gk >= 8 && gk < 16) ? 1 : 0;
            int wsel = (gk < 8) ? gk : gk - 8;
            int kk = gk & 7;
            uint32_t a0[2], a1[2], a2[2], a3[2];
#pragma unroll
            for (int mt = 0; mt < 2; mt++) {
                uint32_t addr = sb + (uint32_t)(PSM_A + part * 16384 + (kk >> 2) * 8192)
                    + SWZ((uint32_t)(((mbase + mt) * 16 + (lane & 15)) * 128
                                     + ((lane >> 4) << 4) + (kk & 3) * 32));
                ldmatrix4(a0[mt], a1[mt], a2[mt], a3[mt], addr);
            }
#pragma unroll
            for (int nn = 0; nn < 4; nn++) {
                uint2 bv = Wfs[(size_t)(wsel * 16 + nbase + nn) * 32 + lane];
#pragma unroll
                for (int mt = 0; mt < 2; mt++)
                    mma16816h(acc[mt][nn], a0[mt], a1[mt], a2[mt], a3[mt], bv.x, bv.y);
            }
        }
        __syncthreads();

        {
            int c0 = (lane & 3) * 2;
#pragma unroll
            for (int mt = 0; mt < 2; mt++) {
                int r0 = (mbase + mt) * 16 + (lane >> 2);
#pragma unroll
                for (int nn = 0; nn < 4; nn++) {
                    int col = (nbase + nn) * 8 + c0;
                    St[col * 65 + r0]           = acc[mt][nn][0];
                    St[(col + 1) * 65 + r0]     = acc[mt][nn][1];
                    St[col * 65 + r0 + 8]       = acc[mt][nn][2];
                    St[(col + 1) * 65 + r0 + 8] = acc[mt][nn][3];
                }
            }
        }
        __syncthreads();

        {
            float* dst = g_proj + (size_t)l * 3072 * 64 + (size_t)ntile * 128 * 64;
#pragma unroll
            for (int i = 0; i < 32; i++) {
                int q = t + i * 256;
                dst[q] = St[(q >> 6) * 65 + (q & 63)];
            }
        }
        __syncthreads();
    }
}

// ---------------- K2: scan (R13 skeleton, single fp16 W, N=16) ----------------------
// 128 CTAs, JB=8. Group g = blockIdx.x>>4 owns A chunk g. 16 warps: kg = wid>>1,
// mg = wid&1 (32 of 64 rows). N = 16 cols = [a(8) | c(8)]. FULL[kg] single completion
// per step (parity l&1); per-group monotonic counters; h double-buffered.
#define OFF_FULL   0
#define OFF_W      1024    // 64 gk x 2 n8 x 32 lanes x 8B = 32KB
#define OFF_SLOTS  33792   // 8 x 16384 = 128KB
#define OFF_RED    164864  // 4 x 64 x 17 x 4 = 17408
#define SMEM_SCAN  (164864 + 4 * 64 * 17 * 4)

__global__ void __launch_bounds__(NT, 1)
scan_tc(const float* __restrict__ Wmm, const __grid_constant__ CUtensorMap tmap) {
    extern __shared__ char smem[];
    uint32_t sb = smem_u32(smem);
    float* RED = (float*)(smem + OFF_RED);
    uint2* Wf  = (uint2*)(smem + OFF_W);
    int t = threadIdx.x, wid = t >> 5, lane = t & 31;
    int kg = wid >> 1, mg = wid & 1;
    int j0 = blockIdx.x * JB;
    int mygrp = blockIdx.x >> 4;

    if (t == 0) {
#pragma unroll
        for (int c = 0; c < 8; c++) MBAR_INIT(sb + OFF_FULL + c * 8, 1);
    }

    // W fragments (fp16 single) in smem: [gk 64][n8 2][lane 32]
    // n_local = n8*8 + lane>>2 in 0..15: 0-7 -> a cols j0+n, 8-15 -> c cols MEM+j0+n-8
    for (int idx = t; idx < 64 * 2 * 32; idx += NT) {
        int ln = idx & 31, n8 = (idx >> 5) & 1, gk = idx >> 6;
        int n_local = n8 * 8 + (ln >> 2);
        int col = (n_local < 8) ? (j0 + n_local) : (MEM + j0 + n_local - 8);
        int k0 = gk * 16 + (ln & 3) * 2;
        const float* wp = Wmm + (size_t)k0 * 2048;
        Wf[idx] = make_uint2(packh(wp[col], wp[2048 + col], false),
                             packh(wp[8 * 2048 + col], wp[9 * 2048 + col], false));
    }

    // init h = 0 into buffer 0 (own 8 columns)
    int b  = t >> 3;
    int jj = t & 7;
    int j  = j0 + jj;
    g_hA[b * MEM + j] = __float2half(0.0f);
    float hreg = 0.0f;
    __syncthreads();
    if (t == 0) {
        __threadfence();
        atomicAdd(&g_grp[mygrp * 64], 1u);
    }

    int q = kg & 3;
    int redbar = 4 + q;
    uint32_t myfull = sb + OFF_FULL + kg * 8;
    uint32_t myslot = sb + OFF_SLOTS + (uint32_t)kg * 16384u;
    int lbase = (lane & 15) * 128 + ((lane >> 4) << 4);
    volatile unsigned int* mycnt = (volatile unsigned int*)&g_grp[kg * 64];

    for (int l = 0; l < L_; l++) {
        int par = l & 1;
        size_t pb = (size_t)l * 3072 * 64;
        float ia = __ldg(&g_proj[pb + (size_t)j * 64 + b]);
        float ic = __ldg(&g_proj[pb + (size_t)(MEM + j) * 64 + b]);
        float io = __ldg(&g_proj[pb + (size_t)(2 * MEM + j) * 64 + b]);

        // JIT producer: mg0-lane0 of each kg polls its group, issues its chunk
        if (mg == 0 && lane == 0) {
            unsigned int tgt = 16u * (unsigned int)(l + 1);
            while (*mycnt < tgt) { }
            __threadfence();
            FENCE_ASYNC_ALL();
            MBAR_EXPECT_TX(myfull, 16384);
            TMA_LD(myslot,        &tmap, kg * 128,      par * 64, 0, myfull);
            TMA_LD(myslot + 8192, &tmap, kg * 128 + 64, par * 64, 0, myfull);
        }

        float acc[2][2][4];
#pragma unroll
        for (int a = 0; a < 2; a++)
#pragma unroll
            for (int b2 = 0; b2 < 2; b2++)
#pragma unroll
                for (int c = 0; c < 4; c++) acc[a][b2][c] = 0.0f;

        MBAR_WAIT(myfull, par);

#pragma unroll
        for (int kk = 0; kk < 8; kk++) {
            const uint2* wp = Wf + (size_t)((kg * 8 + kk) * 2) * 32 + lane;
            uint2 bv0 = wp[0];
            uint2 bv1 = wp[32];
            uint32_t kbase = myslot + (uint32_t)((kk >> 2) * 8192);
            uint32_t loff  = (uint32_t)SWZ(lbase + (kk & 3) * 32);
#pragma unroll
            for (int mt = 0; mt < 2; mt++) {
                uint32_t addr = kbase + (uint32_t)((mg * 2 + mt) * 2048) + loff;
                uint32_t a0, a1, a2, a3;
                ldmatrix4(a0, a1, a2, a3, addr);
                mma16816h(acc[mt][0], a0, a1, a2, a3, bv0.x, bv0.y);
                mma16816h(acc[mt][1], a0, a1, a2, a3, bv1.x, bv1.y);
            }
        }

        // RED: kg<4 write buffer q, kg>=4 accumulate (named barrier per q)
        {
            float* rp = RED + (size_t)q * (64 * 17);
            int r0 = mg * 32 + (lane >> 2);
            int c0 = (lane & 3) * 2;
            if (kg < 4) {
#pragma unroll
                for (int mt = 0; mt < 2; mt++)
#pragma unroll
                    for (int np = 0; np < 2; np++) {
                        float* qp = rp + (r0 + mt * 16) * 17 + np * 8 + c0;
                        qp[0]          = acc[mt][np][0];
                        qp[1]          = acc[mt][np][1];
                        qp[8 * 17]     = acc[mt][np][2];
                        qp[8 * 17 + 1] = acc[mt][np][3];
                    }
                BAR_ARRIVE(redbar, 128);
            } else {
                BAR_SYNC(redbar, 128);
#pragma unroll
                for (int mt = 0; mt < 2; mt++)
#pragma unroll
                    for (int np = 0; np < 2; np++) {
                        float* qp = rp + (r0 + mt * 16) * 17 + np * 8 + c0;
                        qp[0]          += acc[mt][np][0];
                        qp[1]          += acc[mt][np][1];
                        qp[8 * 17]     += acc[mt][np][2];
                        qp[8 * 17 + 1] += acc[mt][np][3];
                    }
            }
        }
        __syncthreads();

        // combine + nBRC update; write h to buffer (l+1)&1
        {
            float ma = 0.0f, mc = 0.0f;
#pragma unroll
            for (int qq = 0; qq < 4; qq++) {
                const float* rq = RED + (size_t)qq * (64 * 17);
                ma += rq[b * 17 + jj];
                mc += rq[b * 17 + 8 + jj];
            }
            float a  = 1.0f + tanh_acc(ia + ma);
            float cg = sigmoid_acc(ic + mc);
            float hn = cg * hreg + (1.0f - cg) * tanh_acc(io + a * hreg);
            hreg = hn;
            g_hA[(((l + 1) & 1) * 64 + b) * MEM + j] = __float2half(hn);
            g_mem[(size_t)l * (MEM * B_) + (size_t)j * B_ + b] = hn;
        }
        __syncthreads();

        if (t == 0) {
            __threadfence();
            atomicAdd(&g_grp[mygrp * 64], 1u);
        }
    }
}

// ---------------- K3: logits + softmax (4 timesteps/block) --------------------------
__global__ void __launch_bounds__(256) logits_kernel(const float* __restrict__ Wact,
                                                     const float* __restrict__ bact,
                                                     float* __restrict__ out) {
    __shared__ float Wa[MEM * DEC];
    int t = threadIdx.x;
    int l = blockIdx.x * 4 + (t >> 6);
    int b = t & 63;
    for (int idx = t; idx < MEM * DEC; idx += 256) Wa[idx] = Wact[idx];
    __syncthreads();

    float a0 = bact[0], a1 = bact[1], a2 = bact[2];
    const float* mp = g_mem + (size_t)l * MEM * B_ + b;
#pragma unroll 8
    for (int k = 0; k < MEM; k++) {
        float v = mp[(size_t)k * B_];
        a0 += v * Wa[k * 3 + 0];
        a1 += v * Wa[k * 3 + 1];
        a2 += v * Wa[k * 3 + 2];
    }
    float m  = fmaxf(a0, fmaxf(a1, a2));
    float e0 = __expf(a0 - m), e1 = __expf(a1 - m), e2 = __expf(a2 - m);
    float inv = 1.0f / (e0 + e1 + e2);
    size_t ob = ((size_t)b * L_ + l) * DEC;
    out[ob + 0] = e0 * inv;
    out[ob + 1] = e1 * inv;
    out[ob + 2] = e2 * inv;
}

// ---------------- launch --------------------------------------------------------------
typedef CUresult (*PFN_tmapEncode)(
    CUtensorMap*, CUtensorMapDataType, cuuint32_t, void*,
    const cuuint64_t*, const cuuint64_t*, const cuuint32_t*, const cuuint32_t*,
    CUtensorMapInterleave, CUtensorMapSwizzle, CUtensorMapL2promotion,
    CUtensorMapFloatOOBfill);

extern "C" void kernel_launch(void* const* d_in, const int* in_sizes, int n_in,
                              void* d_out, int out_size) {
    (void)in_sizes; (void)n_in; (void)out_size;
    const float* x   = (const float*)d_in[0];
    const float* Ws  = (const float*)d_in[1];
    const float* bs  = (const float*)d_in[2];
    const float* Wim = (const float*)d_in[3];
    const float* Wmm = (const float*)d_in[4];
    const float* Wac = (const float*)d_in[5];
    const float* bac = (const float*)d_in[6];
    float* out = (float*)d_out;

    void* hs_ptr = nullptr;
    cudaGetSymbolAddress(&hs_ptr, g_hA);
    PFN_tmapEncode enc = nullptr;
    cudaDriverEntryPointQueryResult qr;
    cudaGetDriverEntryPoint("cuTensorMapEncodeTiled", (void**)&enc,
                            cudaEnableDefault, &qr);
    CUtensorMap tmap;
    {
        cuuint64_t dims[3]    = {MEM, 128, 1};
        cuuint64_t strides[2] = {MEM * 2, (cuuint64_t)MEM * 2 * 128};
        cuuint32_t box[3]     = {64, 64, 1};
        cuuint32_t es[3]      = {1, 1, 1};
        enc(&tmap, CU_TENSOR_MAP_DATA_TYPE_FLOAT16, 3, hs_ptr,
            dims, strides, box, es,
            CU_TENSOR_MAP_INTERLEAVE_NONE, CU_TENSOR_MAP_SWIZZLE_128B,
            CU_TENSOR_MAP_L2_PROMOTION_L2_128B, CU_TENSOR_MAP_FLOAT_OOB_FILL_NONE);
    }

    cudaFuncSetAttribute(proj_tc,  cudaFuncAttributeMaxDynamicSharedMemorySize, PSM_TOT);
    cudaFuncSetAttribute(scan_tc,  cudaFuncAttributeMaxDynamicSharedMemorySize, SMEM_SCAN);

    reset_kernel<<<1, 512>>>();
    sense_kernel<<<B_ * L_ / 8, 128>>>(x, Ws, bs);
    wprep_kernel<<<24, 256>>>(Wim);
    proj_tc<<<dim3(24, 256), 256, PSM_TOT>>>();
    scan_tc<<<NCTA, NT, SMEM_SCAN>>>(Wmm, tmap);
    logits_kernel<<<L_ / 4, 256>>>(Wac, bac, out);
}

// round 16
// speedup vs baseline: 1.4448x; 1.0632x over previous
#include <cuda.h>
#include <cuda_runtime.h>
#include <cuda_bf16.h>
#include <cuda_fp16.h>
#include <math.h>
#include <stdint.h>

#define B_    64
#define L_    1024
#define N_    64
#define INSZ  128
#define MEM   1024
#define DEC   3

#define NCTA  128
#define NT    512
#define JB    8

// ---------------- scratch ----------------------------------------------------
__device__ __half g_ih  [(size_t)L_ * 2 * B_ * INSZ];         // [l][part hi/lo][b][k]
__device__ uint2  g_wfrag[24 * 4096];                         // W_im hi fragments (768KB)
__device__ float g_proj [(size_t)L_ * 3 * MEM * B_];          // [l][col][b]
__device__ __half g_hA  [2 * 64 * MEM];                       // double-buffered h fp16
__device__ float g_mem  [(size_t)L_ * MEM * B_];              // [l][j][b]
__device__ unsigned int g_grp[8 * 64];                        // per-group monotonic counters

// ---------------- PTX helpers ------------------------------------------------
__device__ __forceinline__ uint32_t smem_u32(const void* p) {
    uint32_t a;
    asm("{ .reg .u64 t; cvta.to.shared.u64 t, %1; cvt.u32.u64 %0, t; }" : "=r"(a) : "l"(p));
    return a;
}
#define SWZ(o) ((o) ^ (((o) >> 3) & 0x70))

#define MBAR_INIT(a, c) asm volatile("mbarrier.init.shared.b64 [%0], %1;" :: "r"((uint32_t)(a)), "r"((uint32_t)(c)) : "memory")
#define MBAR_EXPECT_TX(a, n) asm volatile("mbarrier.arrive.expect_tx.shared.b64 _, [%0], %1;" :: "r"((uint32_t)(a)), "r"((uint32_t)(n)) : "memory")

#define MBAR_WAIT(a, par) do { \
    uint32_t _m = (uint32_t)(a); uint32_t _p = (uint32_t)(par); uint32_t _d; \
    asm volatile("{\n\t.reg .pred p;\n\t" \
        "mbarrier.try_wait.parity.acquire.cta.shared::cta.b64 p, [%1], %2;\n\t" \
        "selp.b32 %0, 1, 0, p;\n\t}" : "=r"(_d) : "r"(_m), "r"(_p) : "memory"); \
    if (!_d) { \
        asm volatile("{\n\t.reg .pred P1;\n\tWL_%=:\n\t" \
            "mbarrier.try_wait.parity.acquire.cta.shared::cta.b64 P1, [%0], %1, 0x989680;\n\t" \
            "@P1 bra.uni WD_%=;\n\tbra.uni WL_%=;\n\tWD_%=:\n\t}" \
            :: "r"(_m), "r"(_p) : "memory"); \
    } } while (0)

#define TMA_LD(dst, tm, cx, cy, cz, mbar) \
    asm volatile("cp.async.bulk.tensor.3d.shared::cta.global.tile.mbarrier::complete_tx::bytes " \
        "[%0], [%1, {%2, %3, %4}], [%5];" \
        :: "r"((uint32_t)(dst)), "l"(tm), "r"((int32_t)(cx)), "r"((int32_t)(cy)), "r"((int32_t)(cz)), \
           "r"((uint32_t)(mbar)) : "memory")

#define FENCE_ASYNC_ALL() asm volatile("fence.proxy.async;" ::: "memory")
#define BAR_ARRIVE(id, cnt) asm volatile("bar.arrive %0, %1;" :: "r"(id), "r"(cnt) : "memory")
#define BAR_SYNC(id, cnt)   asm volatile("bar.sync %0, %1;"   :: "r"(id), "r"(cnt) : "memory")

__device__ __forceinline__ void ldmatrix4(uint32_t& a0, uint32_t& a1, uint32_t& a2, uint32_t& a3,
                                          uint32_t addr) {
    asm volatile("ldmatrix.sync.aligned.m8n8.x4.shared.b16 {%0,%1,%2,%3}, [%4];"
        : "=r"(a0), "=r"(a1), "=r"(a2), "=r"(a3) : "r"(addr));
}
__device__ __forceinline__ void mma16816h(float* d, uint32_t a0, uint32_t a1, uint32_t a2, uint32_t a3,
                                          uint32_t b0, uint32_t b1) {
    asm volatile("mma.sync.aligned.m16n8k16.row.col.f32.f16.f16.f32 "
        "{%0,%1,%2,%3}, {%4,%5,%6,%7}, {%8,%9}, {%0,%1,%2,%3};"
        : "+f"(d[0]), "+f"(d[1]), "+f"(d[2]), "+f"(d[3])
        : "r"(a0), "r"(a1), "r"(a2), "r"(a3), "r"(b0), "r"(b1));
}

__device__ __forceinline__ float tanh_acc(float x) {
    float ax = fabsf(x);
    float e  = __expf(-2.0f * ax);
    float t  = (1.0f - e) / (1.0f + e);
    return copysignf(t, x);
}
__device__ __forceinline__ float sigmoid_acc(float z) {
    return 1.0f / (1.0f + __expf(-z));
}
__device__ __forceinline__ uint32_t packh(float x, float y, bool lo) {
    __half xh = __float2half(x), yh = __float2half(y);
    if (lo) {
        xh = __float2half(x - __half2float(xh));
        yh = __float2half(y - __half2float(yh));
    }
    return ((uint32_t)__half_as_ushort(yh) << 16) | (uint32_t)__half_as_ushort(xh);
}

__global__ void reset_kernel() {
    int t = threadIdx.x;
    if (t < 512) g_grp[t] = 0u;
}

// ---------------- K1a: sense (8 tokens/block) -> fp16 hi/lo -----------------------
__global__ void __launch_bounds__(128) sense_kernel(const float* __restrict__ x,
                                                    const float* __restrict__ Ws,
                                                    const float* __restrict__ bs) {
    __shared__ float xs[8][N_];
    int t = threadIdx.x;
    int bl0 = blockIdx.x * 8;
#pragma unroll
    for (int i = 0; i < 4; i++) {
        int idx = t + i * 128;
        xs[idx >> 6][idx & 63] = x[(size_t)bl0 * N_ + idx];
    }
    __syncthreads();
    float acc[8];
    float bias = bs[t];
#pragma unroll
    for (int i = 0; i < 8; i++) acc[i] = bias;
    for (int n = 0; n < N_; n++) {
        float w = Ws[n * INSZ + t];
#pragma unroll
        for (int i = 0; i < 8; i++) acc[i] += xs[i][n] * w;
    }
#pragma unroll
    for (int i = 0; i < 8; i++) {
        int bl = bl0 + i;
        int b = bl >> 10, l = bl & (L_ - 1);
        __half hh = __float2half(acc[i]);
        __half hl = __float2half(acc[i] - __half2float(hh));
        g_ih[(((size_t)l * 2 + 0) * B_ + b) * INSZ + t] = hh;
        g_ih[(((size_t)l * 2 + 1) * B_ + b) * INSZ + t] = hl;
    }
}

// ---------------- K1b-pre: W_im hi fragments ---------------------------------------
__global__ void __launch_bounds__(256) wprep_kernel(const float* __restrict__ Wim) {
    int ntile = blockIdx.x;
    int t = threadIdx.x;
    for (int q = t; q < 8 * 16 * 32; q += 256) {
        int lane = q & 31, n8 = (q >> 5) & 15, wsel = q >> 9;   // wsel 0..7
        int n = ntile * 128 + n8 * 8 + (lane >> 2);
        int k0 = wsel * 16 + (lane & 3) * 2;
        const float* wp = Wim + (size_t)k0 * 3072 + n;
        g_wfrag[(size_t)ntile * 4096 + q] =
            make_uint2(packh(wp[0], wp[3072], false),
                       packh(wp[8 * 3072], wp[9 * 3072], false));
    }
}

// ---------------- K1b: proj via mma.sync (16 gk: Ah*Wh + Al*Wh) ---------------------
#define PSM_WF 0
#define PSM_A  32768
#define PSM_ST 65536
#define PSM_TOT (65536 + 128 * 65 * 4)
__global__ void __launch_bounds__(256) proj_tc() {
    extern __shared__ char sm[];
    uint32_t sb = smem_u32(sm);
    const uint2* Wfs = (const uint2*)(sm + PSM_WF);
    float* St = (float*)(sm + PSM_ST);
    int ntile = blockIdx.x;
    int l0 = blockIdx.y * 4;
    int t = threadIdx.x, w = t >> 5, lane = t & 31;
    int mbase = (w & 1) * 2;
    int nbase = (w >> 1) * 4;

    {
        const uint4* wsrc = (const uint4*)(g_wfrag + (size_t)ntile * 4096);
#pragma unroll
        for (int i = 0; i < 8; i++)
            ((uint4*)(sm + PSM_WF))[t + i * 256] = wsrc[t + i * 256];
    }
    __syncthreads();

    for (int li = 0; li < 4; li++) {
        int l = l0 + li;
        const uint4* asrc = (const uint4*)(g_ih + (size_t)l * 2 * B_ * INSZ);
#pragma unroll
        for (int i = 0; i < 8; i++) {
            int q = t + i * 256;
            int part = q >> 10;
            int rb = (q >> 4) & 63;
            int k0 = (q & 15) * 8;
            uint32_t dst = (uint32_t)(PSM_A + part * 16384 + (k0 >> 6) * 8192)
                         + SWZ((uint32_t)(rb * 128 + (k0 & 63) * 2));
            *(uint4*)(sm + dst) = asrc[q];
        }
        __syncthreads();

        float acc[2][4][4];
#pragma unroll
        for (int a = 0; a < 2; a++)
#pragma unroll
            for (int b2 = 0; b2 < 4; b2++)
#pragma unroll
                for (int c = 0; c < 4; c++) acc[a][b2][c] = 0.0f;

#pragma unroll
        for (int gk = 0; gk < 16; gk++) {
            int part = gk >> 3;          // 0: Ah, 1: Al (both x Wh)
            int wsel = gk & 7;
            int kk = gk & 7;
            uint32_t a0[2], a1[2], a2[2], a3[2];
#pragma unroll
            for (int mt = 0; mt < 2; mt++) {
                uint32_t addr = sb + (uint32_t)(PSM_A + part * 16384 + (kk >> 2) * 8192)
                    + SWZ((uint32_t)(((mbase + mt) * 16 + (lane & 15)) * 128
                                     + ((lane >> 4) << 4) + (kk & 3) * 32));
                ldmatrix4(a0[mt], a1[mt], a2[mt], a3[mt], addr);
            }
#pragma unroll
            for (int nn = 0; nn < 4; nn++) {
                uint2 bv = Wfs[(size_t)(wsel * 16 + nbase + nn) * 32 + lane];
#pragma unroll
                for (int mt = 0; mt < 2; mt++)
                    mma16816h(acc[mt][nn], a0[mt], a1[mt], a2[mt], a3[mt], bv.x, bv.y);
            }
        }
        __syncthreads();

        {
            int c0 = (lane & 3) * 2;
#pragma unroll
            for (int mt = 0; mt < 2; mt++) {
                int r0 = (mbase + mt) * 16 + (lane >> 2);
#pragma unroll
                for (int nn = 0; nn < 4; nn++) {
                    int col = (nbase + nn) * 8 + c0;
                    St[col * 65 + r0]           = acc[mt][nn][0];
                    St[(col + 1) * 65 + r0]     = acc[mt][nn][1];
                    St[col * 65 + r0 + 8]       = acc[mt][nn][2];
                    St[(col + 1) * 65 + r0 + 8] = acc[mt][nn][3];
                }
            }
        }
        __syncthreads();

        {
            float* dst = g_proj + (size_t)l * 3072 * 64 + (size_t)ntile * 128 * 64;
#pragma unroll
            for (int i = 0; i < 32; i++) {
                int q = t + i * 256;
                dst[q] = St[(q >> 6) * 65 + (q & 63)];
            }
        }
        __syncthreads();
    }
}

// ---------------- K2: scan (R15 skeleton; W frags + ldmatrix addrs in registers) ----
#define OFF_FULL   0
#define OFF_SLOTS  1024    // 8 x 16384 = 128KB
#define OFF_RED    132096  // 4 x 64 x 17 x 4 = 17408
#define SMEM_SCAN  (132096 + 4 * 64 * 17 * 4)

__global__ void __launch_bounds__(NT, 1)
scan_tc(const float* __restrict__ Wmm, const __grid_constant__ CUtensorMap tmap) {
    extern __shared__ char smem[];
    uint32_t sb = smem_u32(smem);
    float* RED = (float*)(smem + OFF_RED);
    int t = threadIdx.x, wid = t >> 5, lane = t & 31;
    int kg = wid >> 1, mg = wid & 1;
    int j0 = blockIdx.x * JB;
    int mygrp = blockIdx.x >> 4;

    if (t == 0) {
#pragma unroll
        for (int c = 0; c < 8; c++) MBAR_INIT(sb + OFF_FULL + c * 8, 1);
    }

    // W fragments (fp16 single) straight into registers: per (kg, kk, lane)
    uint2 wreg[8][2];
    {
        int nl = lane >> 2;       // 0..7
#pragma unroll
        for (int kk = 0; kk < 8; kk++) {
            int k0 = kg * 128 + kk * 16 + (lane & 3) * 2;
            const float* wp = Wmm + (size_t)k0 * 2048;
            int colA = j0 + nl;
            int colC = MEM + j0 + nl;
            wreg[kk][0] = make_uint2(packh(wp[colA], wp[2048 + colA], false),
                                     packh(wp[8 * 2048 + colA], wp[9 * 2048 + colA], false));
            wreg[kk][1] = make_uint2(packh(wp[colC], wp[2048 + colC], false),
                                     packh(wp[8 * 2048 + colC], wp[9 * 2048 + colC], false));
        }
    }

    // init h = 0 into buffer 0 (own 8 columns)
    int b  = t >> 3;
    int jj = t & 7;
    int j  = j0 + jj;
    g_hA[b * MEM + j] = __float2half(0.0f);
    float hreg = 0.0f;
    __syncthreads();
    if (t == 0) {
        __threadfence();
        atomicAdd(&g_grp[mygrp * 64], 1u);
    }

    int q = kg & 3;
    int redbar = 4 + q;
    uint32_t myfull = sb + OFF_FULL + kg * 8;
    uint32_t myslot = sb + OFF_SLOTS + (uint32_t)kg * 16384u;
    volatile unsigned int* mycnt = (volatile unsigned int*)&g_grp[kg * 64];

    // precomputed ldmatrix addresses (loop-invariant)
    uint32_t addrR[8][2];
    {
        int lbase = (lane & 15) * 128 + ((lane >> 4) << 4);
#pragma unroll
        for (int kk = 0; kk < 8; kk++) {
            uint32_t kbase = myslot + (uint32_t)((kk >> 2) * 8192);
            uint32_t loff  = (uint32_t)SWZ(lbase + (kk & 3) * 32);
#pragma unroll
            for (int mt = 0; mt < 2; mt++)
                addrR[kk][mt] = kbase + (uint32_t)((mg * 2 + mt) * 2048) + loff;
        }
    }

    for (int l = 0; l < L_; l++) {
        int par = l & 1;
        size_t pb = (size_t)l * 3072 * 64;
        float ia = __ldg(&g_proj[pb + (size_t)j * 64 + b]);
        float ic = __ldg(&g_proj[pb + (size_t)(MEM + j) * 64 + b]);
        float io = __ldg(&g_proj[pb + (size_t)(2 * MEM + j) * 64 + b]);

        // JIT producer: mg0-lane0 of each kg polls its group, issues its chunk
        if (mg == 0 && lane == 0) {
            unsigned int tgt = 16u * (unsigned int)(l + 1);
            while (*mycnt < tgt) { }
            __threadfence();
            FENCE_ASYNC_ALL();
            MBAR_EXPECT_TX(myfull, 16384);
            TMA_LD(myslot,        &tmap, kg * 128,      par * 64, 0, myfull);
            TMA_LD(myslot + 8192, &tmap, kg * 128 + 64, par * 64, 0, myfull);
        }

        float acc[2][2][4];
#pragma unroll
        for (int a = 0; a < 2; a++)
#pragma unroll
            for (int b2 = 0; b2 < 2; b2++)
#pragma unroll
                for (int c = 0; c < 4; c++) acc[a][b2][c] = 0.0f;

        MBAR_WAIT(myfull, par);

#pragma unroll
        for (int kk = 0; kk < 8; kk++) {
#pragma unroll
            for (int mt = 0; mt < 2; mt++) {
                uint32_t a0, a1, a2, a3;
                ldmatrix4(a0, a1, a2, a3, addrR[kk][mt]);
                mma16816h(acc[mt][0], a0, a1, a2, a3, wreg[kk][0].x, wreg[kk][0].y);
                mma16816h(acc[mt][1], a0, a1, a2, a3, wreg[kk][1].x, wreg[kk][1].y);
            }
        }

        // RED: kg<4 write buffer q, kg>=4 accumulate (named barrier per q)
        {
            float* rp = RED + (size_t)q * (64 * 17);
            int r0 = mg * 32 + (lane >> 2);
            int c0 = (lane & 3) * 2;
            if (kg < 4) {
#pragma unroll
                for (int mt = 0; mt < 2; mt++)
#pragma unroll
                    for (int np = 0; np < 2; np++) {
                        float* qp = rp + (r0 + mt * 16) * 17 + np * 8 + c0;
                        qp[0]          = acc[mt][np][0];
                        qp[1]          = acc[mt][np][1];
                        qp[8 * 17]     = acc[mt][np][2];
                        qp[8 * 17 + 1] = acc[mt][np][3];
                    }
                BAR_ARRIVE(redbar, 128);
            } else {
                BAR_SYNC(redbar, 128);
#pragma unroll
                for (int mt = 0; mt < 2; mt++)
#pragma unroll
                    for (int np = 0; np < 2; np++) {
                        float* qp = rp + (r0 + mt * 16) * 17 + np * 8 + c0;
                        qp[0]          += acc[mt][np][0];
                        qp[1]          += acc[mt][np][1];
                        qp[8 * 17]     += acc[mt][np][2];
                        qp[8 * 17 + 1] += acc[mt][np][3];
                    }
            }
        }
        __syncthreads();

        // combine + nBRC update; write h to buffer (l+1)&1
        {
            float ma = 0.0f, mc = 0.0f;
#pragma unroll
            for (int qq = 0; qq < 4; qq++) {
                const float* rq = RED + (size_t)qq * (64 * 17);
                ma += rq[b * 17 + jj];
                mc += rq[b * 17 + 8 + jj];
            }
            float a  = 1.0f + tanh_acc(ia + ma);
            float cg = sigmoid_acc(ic + mc);
            float hn = cg * hreg + (1.0f - cg) * tanh_acc(io + a * hreg);
            hreg = hn;
            g_hA[(((l + 1) & 1) * 64 + b) * MEM + j] = __float2half(hn);
            g_mem[(size_t)l * (MEM * B_) + (size_t)j * B_ + b] = hn;
        }
        __syncthreads();

        if (t == 0) {
            __threadfence();
            atomicAdd(&g_grp[mygrp * 64], 1u);
        }
    }
}

// ---------------- K3: logits + softmax (4 timesteps/block) --------------------------
__global__ void __launch_bounds__(256) logits_kernel(const float* __restrict__ Wact,
                                                     const float* __restrict__ bact,
                                                     float* __restrict__ out) {
    __shared__ float Wa[MEM * DEC];
    int t = threadIdx.x;
    int l = blockIdx.x * 4 + (t >> 6);
    int b = t & 63;
    for (int idx = t; idx < MEM * DEC; idx += 256) Wa[idx] = Wact[idx];
    __syncthreads();

    float a0 = bact[0], a1 = bact[1], a2 = bact[2];
    const float* mp = g_mem + (size_t)l * MEM * B_ + b;
#pragma unroll 8
    for (int k = 0; k < MEM; k++) {
        float v = mp[(size_t)k * B_];
        a0 += v * Wa[k * 3 + 0];
        a1 += v * Wa[k * 3 + 1];
        a2 += v * Wa[k * 3 + 2];
    }
    float m  = fmaxf(a0, fmaxf(a1, a2));
    float e0 = __expf(a0 - m), e1 = __expf(a1 - m), e2 = __expf(a2 - m);
    float inv = 1.0f / (e0 + e1 + e2);
    size_t ob = ((size_t)b * L_ + l) * DEC;
    out[ob + 0] = e0 * inv;
    out[ob + 1] = e1 * inv;
    out[ob + 2] = e2 * inv;
}

// ---------------- launch --------------------------------------------------------------
typedef CUresult (*PFN_tmapEncode)(
    CUtensorMap*, CUtensorMapDataType, cuuint32_t, void*,
    const cuuint64_t*, const cuuint64_t*, const cuuint32_t*, const cuuint32_t*,
    CUtensorMapInterleave, CUtensorMapSwizzle, CUtensorMapL2promotion,
    CUtensorMapFloatOOBfill);

extern "C" void kernel_launch(void* const* d_in, const int* in_sizes, int n_in,
                              void* d_out, int out_size) {
    (void)in_sizes; (void)n_in; (void)out_size;
    const float* x   = (const float*)d_in[0];
    const float* Ws  = (const float*)d_in[1];
    const float* bs  = (const float*)d_in[2];
    const float* Wim = (const float*)d_in[3];
    const float* Wmm = (const float*)d_in[4];
    const float* Wac = (const float*)d_in[5];
    const float* bac = (const float*)d_in[6];
    float* out = (float*)d_out;

    void* hs_ptr = nullptr;
    cudaGetSymbolAddress(&hs_ptr, g_hA);
    PFN_tmapEncode enc = nullptr;
    cudaDriverEntryPointQueryResult qr;
    cudaGetDriverEntryPoint("cuTensorMapEncodeTiled", (void**)&enc,
                            cudaEnableDefault, &qr);
    CUtensorMap tmap;
    {
        cuuint64_t dims[3]    = {MEM, 128, 1};
        cuuint64_t strides[2] = {MEM * 2, (cuuint64_t)MEM * 2 * 128};
        cuuint32_t box[3]     = {64, 64, 1};
        cuuint32_t es[3]      = {1, 1, 1};
        enc(&tmap, CU_TENSOR_MAP_DATA_TYPE_FLOAT16, 3, hs_ptr,
            dims, strides, box, es,
            CU_TENSOR_MAP_INTERLEAVE_NONE, CU_TENSOR_MAP_SWIZZLE_128B,
            CU_TENSOR_MAP_L2_PROMOTION_L2_128B, CU_TENSOR_MAP_FLOAT_OOB_FILL_NONE);
    }

    cudaFuncSetAttribute(proj_tc,  cudaFuncAttributeMaxDynamicSharedMemorySize, PSM_TOT);
    cudaFuncSetAttribute(scan_tc,  cudaFuncAttributeMaxDynamicSharedMemorySize, SMEM_SCAN);

    reset_kernel<<<1, 512>>>();
    sense_kernel<<<B_ * L_ / 8, 128>>>(x, Ws, bs);
    wprep_kernel<<<24, 256>>>(Wim);
    proj_tc<<<dim3(24, 256), 256, PSM_TOT>>>();
    scan_tc<<<NCTA, NT, SMEM_SCAN>>>(Wmm, tmap);
    logits_kernel<<<L_ / 4, 256>>>(Wac, bac, out);
}

// round 17
// speedup vs baseline: 1.5244x; 1.0551x over previous
#include <cuda.h>
#include <cuda_runtime.h>
#include <cuda_bf16.h>
#include <cuda_fp16.h>
#include <math.h>
#include <stdint.h>

#define B_    64
#define L_    1024
#define N_    64
#define INSZ  128
#define MEM   1024
#define DEC   3

#define NCTA  128
#define NT    512
#define JB    8

// ---------------- scratch ----------------------------------------------------
__device__ __half g_ih  [(size_t)L_ * 2 * B_ * INSZ];         // [l][part hi/lo][b][k]
__device__ uint2  g_wfrag[24 * 4096];                         // W_im hi fragments (768KB)
__device__ float g_proj [(size_t)L_ * 3 * MEM * B_];          // [l][col][b]
__device__ __half g_hA  [2 * 64 * MEM];                       // double-buffered h fp16
__device__ float g_mem  [(size_t)L_ * MEM * B_];              // [l][j][b]
__device__ unsigned int g_grp[8 * 64];                        // per-group monotonic counters

// ---------------- PTX helpers ------------------------------------------------
__device__ __forceinline__ uint32_t smem_u32(const void* p) {
    uint32_t a;
    asm("{ .reg .u64 t; cvta.to.shared.u64 t, %1; cvt.u32.u64 %0, t; }" : "=r"(a) : "l"(p));
    return a;
}
#define SWZ(o) ((o) ^ (((o) >> 3) & 0x70))

#define MBAR_INIT(a, c) asm volatile("mbarrier.init.shared.b64 [%0], %1;" :: "r"((uint32_t)(a)), "r"((uint32_t)(c)) : "memory")
#define MBAR_EXPECT_TX(a, n) asm volatile("mbarrier.arrive.expect_tx.shared.b64 _, [%0], %1;" :: "r"((uint32_t)(a)), "r"((uint32_t)(n)) : "memory")

#define MBAR_WAIT(a, par) do { \
    uint32_t _m = (uint32_t)(a); uint32_t _p = (uint32_t)(par); uint32_t _d; \
    asm volatile("{\n\t.reg .pred p;\n\t" \
        "mbarrier.try_wait.parity.acquire.cta.shared::cta.b64 p, [%1], %2;\n\t" \
        "selp.b32 %0, 1, 0, p;\n\t}" : "=r"(_d) : "r"(_m), "r"(_p) : "memory"); \
    if (!_d) { \
        asm volatile("{\n\t.reg .pred P1;\n\tWL_%=:\n\t" \
            "mbarrier.try_wait.parity.acquire.cta.shared::cta.b64 P1, [%0], %1, 0x989680;\n\t" \
            "@P1 bra.uni WD_%=;\n\tbra.uni WL_%=;\n\tWD_%=:\n\t}" \
            :: "r"(_m), "r"(_p) : "memory"); \
    } } while (0)

#define TMA_LD(dst, tm, cx, cy, cz, mbar) \
    asm volatile("cp.async.bulk.tensor.3d.shared::cta.global.tile.mbarrier::complete_tx::bytes " \
        "[%0], [%1, {%2, %3, %4}], [%5];" \
        :: "r"((uint32_t)(dst)), "l"(tm), "r"((int32_t)(cx)), "r"((int32_t)(cy)), "r"((int32_t)(cz)), \
           "r"((uint32_t)(mbar)) : "memory")

#define FENCE_ASYNC_ALL() asm volatile("fence.proxy.async;" ::: "memory")

__device__ __forceinline__ void ldmatrix4(uint32_t& a0, uint32_t& a1, uint32_t& a2, uint32_t& a3,
                                          uint32_t addr) {
    asm volatile("ldmatrix.sync.aligned.m8n8.x4.shared.b16 {%0,%1,%2,%3}, [%4];"
        : "=r"(a0), "=r"(a1), "=r"(a2), "=r"(a3) : "r"(addr));
}
__device__ __forceinline__ void mma16816h(float* d, uint32_t a0, uint32_t a1, uint32_t a2, uint32_t a3,
                                          uint32_t b0, uint32_t b1) {
    asm volatile("mma.sync.aligned.m16n8k16.row.col.f32.f16.f16.f32 "
        "{%0,%1,%2,%3}, {%4,%5,%6,%7}, {%8,%9}, {%0,%1,%2,%3};"
        : "+f"(d[0]), "+f"(d[1]), "+f"(d[2]), "+f"(d[3])
        : "r"(a0), "r"(a1), "r"(a2), "r"(a3), "r"(b0), "r"(b1));
}

__device__ __forceinline__ float tanh_acc(float x) {
    float ax = fabsf(x);
    float e  = __expf(-2.0f * ax);
    float t  = (1.0f - e) / (1.0f + e);
    return copysignf(t, x);
}
__device__ __forceinline__ float sigmoid_acc(float z) {
    return 1.0f / (1.0f + __expf(-z));
}
__device__ __forceinline__ uint32_t packh(float x, float y, bool lo) {
    __half xh = __float2half(x), yh = __float2half(y);
    if (lo) {
        xh = __float2half(x - __half2float(xh));
        yh = __float2half(y - __half2float(yh));
    }
    return ((uint32_t)__half_as_ushort(yh) << 16) | (uint32_t)__half_as_ushort(xh);
}

__global__ void reset_kernel() {
    int t = threadIdx.x;
    if (t < 512) g_grp[t] = 0u;
}

// ---------------- K1a: sense (8 tokens/block) -> fp16 hi/lo -----------------------
__global__ void __launch_bounds__(128) sense_kernel(const float* __restrict__ x,
                                                    const float* __restrict__ Ws,
                                                    const float* __restrict__ bs) {
    __shared__ float xs[8][N_];
    int t = threadIdx.x;
    int bl0 = blockIdx.x * 8;
#pragma unroll
    for (int i = 0; i < 4; i++) {
        int idx = t + i * 128;
        xs[idx >> 6][idx & 63] = x[(size_t)bl0 * N_ + idx];
    }
    __syncthreads();
    float acc[8];
    float bias = bs[t];
#pragma unroll
    for (int i = 0; i < 8; i++) acc[i] = bias;
    for (int n = 0; n < N_; n++) {
        float w = Ws[n * INSZ + t];
#pragma unroll
        for (int i = 0; i < 8; i++) acc[i] += xs[i][n] * w;
    }
#pragma unroll
    for (int i = 0; i < 8; i++) {
        int bl = bl0 + i;
        int b = bl >> 10, l = bl & (L_ - 1);
        __half hh = __float2half(acc[i]);
        __half hl = __float2half(acc[i] - __half2float(hh));
        g_ih[(((size_t)l * 2 + 0) * B_ + b) * INSZ + t] = hh;
        g_ih[(((size_t)l * 2 + 1) * B_ + b) * INSZ + t] = hl;
    }
}

// ---------------- K1b-pre: W_im hi fragments ---------------------------------------
__global__ void __launch_bounds__(256) wprep_kernel(const float* __restrict__ Wim) {
    int ntile = blockIdx.x;
    int t = threadIdx.x;
    for (int q = t; q < 8 * 16 * 32; q += 256) {
        int lane = q & 31, n8 = (q >> 5) & 15, wsel = q >> 9;
        int n = ntile * 128 + n8 * 8 + (lane >> 2);
        int k0 = wsel * 16 + (lane & 3) * 2;
        const float* wp = Wim + (size_t)k0 * 3072 + n;
        g_wfrag[(size_t)ntile * 4096 + q] =
            make_uint2(packh(wp[0], wp[3072], false),
                       packh(wp[8 * 3072], wp[9 * 3072], false));
    }
}

// ---------------- K1b: proj (St aliases dead A region; 2 blocks/SM) -----------------
#define PSM_WF 0
#define PSM_A  32768
#define PSM_TOT (32768 + 128 * 65 * 4)   // St (33280B) aliases A (32KB) and extends past
__global__ void __launch_bounds__(256, 2) proj_tc() {
    extern __shared__ char sm[];
    uint32_t sb = smem_u32(sm);
    const uint2* Wfs = (const uint2*)(sm + PSM_WF);
    float* St = (float*)(sm + PSM_A);
    int ntile = blockIdx.x;
    int l0 = blockIdx.y * 4;
    int t = threadIdx.x, w = t >> 5, lane = t & 31;
    int mbase = (w & 1) * 2;
    int nbase = (w >> 1) * 4;

    {
        const uint4* wsrc = (const uint4*)(g_wfrag + (size_t)ntile * 4096);
#pragma unroll
        for (int i = 0; i < 8; i++)
            ((uint4*)(sm + PSM_WF))[t + i * 256] = wsrc[t + i * 256];
    }
    __syncthreads();

    for (int li = 0; li < 4; li++) {
        int l = l0 + li;
        const uint4* asrc = (const uint4*)(g_ih + (size_t)l * 2 * B_ * INSZ);
#pragma unroll
        for (int i = 0; i < 8; i++) {
            int q = t + i * 256;
            int part = q >> 10;
            int rb = (q >> 4) & 63;
            int k0 = (q & 15) * 8;
            uint32_t dst = (uint32_t)(PSM_A + part * 16384 + (k0 >> 6) * 8192)
                         + SWZ((uint32_t)(rb * 128 + (k0 & 63) * 2));
            *(uint4*)(sm + dst) = asrc[q];
        }
        __syncthreads();

        float acc[2][4][4];
#pragma unroll
        for (int a = 0; a < 2; a++)
#pragma unroll
            for (int b2 = 0; b2 < 4; b2++)
#pragma unroll
                for (int c = 0; c < 4; c++) acc[a][b2][c] = 0.0f;

#pragma unroll
        for (int gk = 0; gk < 16; gk++) {
            int part = gk >> 3;
            int wsel = gk & 7;
            int kk = gk & 7;
            uint32_t a0[2], a1[2], a2[2], a3[2];
#pragma unroll
            for (int mt = 0; mt < 2; mt++) {
                uint32_t addr = sb + (uint32_t)(PSM_A + part * 16384 + (kk >> 2) * 8192)
                    + SWZ((uint32_t)(((mbase + mt) * 16 + (lane & 15)) * 128
                                     + ((lane >> 4) << 4) + (kk & 3) * 32));
                ldmatrix4(a0[mt], a1[mt], a2[mt], a3[mt], addr);
            }
#pragma unroll
            for (int nn = 0; nn < 4; nn++) {
                uint2 bv = Wfs[(size_t)(wsel * 16 + nbase + nn) * 32 + lane];
#pragma unroll
                for (int mt = 0; mt < 2; mt++)
                    mma16816h(acc[mt][nn], a0[mt], a1[mt], a2[mt], a3[mt], bv.x, bv.y);
            }
        }
        __syncthreads();   // all A reads done -> St may overwrite A region

        {
            int c0 = (lane & 3) * 2;
#pragma unroll
            for (int mt = 0; mt < 2; mt++) {
                int r0 = (mbase + mt) * 16 + (lane >> 2);
#pragma unroll
                for (int nn = 0; nn < 4; nn++) {
                    int col = (nbase + nn) * 8 + c0;
                    St[col * 65 + r0]           = acc[mt][nn][0];
                    St[(col + 1) * 65 + r0]     = acc[mt][nn][1];
                    St[col * 65 + r0 + 8]       = acc[mt][nn][2];
                    St[(col + 1) * 65 + r0 + 8] = acc[mt][nn][3];
                }
            }
        }
        __syncthreads();

        {
            float* dst = g_proj + (size_t)l * 3072 * 64 + (size_t)ntile * 128 * 64;
#pragma unroll
            for (int i = 0; i < 32; i++) {
                int q = t + i * 256;
                dst[q] = St[(q >> 6) * 65 + (q & 63)];
            }
        }
        __syncthreads();
    }
}

// ---------------- K2: scan (8 RED buffers, no named barriers) -----------------------
#define OFF_FULL   0
#define OFF_SLOTS  1024    // 8 x 16384 = 128KB
#define OFF_RED    132096  // 8 x 64 x 17 x 4 = 34816
#define SMEM_SCAN  (132096 + 8 * 64 * 17 * 4)

__global__ void __launch_bounds__(NT, 1)
scan_tc(const float* __restrict__ Wmm, const __grid_constant__ CUtensorMap tmap) {
    extern __shared__ char smem[];
    uint32_t sb = smem_u32(smem);
    float* RED = (float*)(smem + OFF_RED);
    int t = threadIdx.x, wid = t >> 5, lane = t & 31;
    int kg = wid >> 1, mg = wid & 1;
    int j0 = blockIdx.x * JB;
    int mygrp = blockIdx.x >> 4;

    if (t == 0) {
#pragma unroll
        for (int c = 0; c < 8; c++) MBAR_INIT(sb + OFF_FULL + c * 8, 1);
    }

    // W fragments (fp16 single) straight into registers
    uint2 wreg[8][2];
    {
        int nl = lane >> 2;
#pragma unroll
        for (int kk = 0; kk < 8; kk++) {
            int k0 = kg * 128 + kk * 16 + (lane & 3) * 2;
            const float* wp = Wmm + (size_t)k0 * 2048;
            int colA = j0 + nl;
            int colC = MEM + j0 + nl;
            wreg[kk][0] = make_uint2(packh(wp[colA], wp[2048 + colA], false),
                                     packh(wp[8 * 2048 + colA], wp[9 * 2048 + colA], false));
            wreg[kk][1] = make_uint2(packh(wp[colC], wp[2048 + colC], false),
                                     packh(wp[8 * 2048 + colC], wp[9 * 2048 + colC], false));
        }
    }

    // init h = 0 into buffer 0 (own 8 columns)
    int b  = t >> 3;
    int jj = t & 7;
    int j  = j0 + jj;
    g_hA[b * MEM + j] = __float2half(0.0f);
    float hreg = 0.0f;
    __syncthreads();
    if (t == 0) {
        __threadfence();
        atomicAdd(&g_grp[mygrp * 64], 1u);
    }

    uint32_t myfull = sb + OFF_FULL + kg * 8;
    uint32_t myslot = sb + OFF_SLOTS + (uint32_t)kg * 16384u;
    volatile unsigned int* mycnt = (volatile unsigned int*)&g_grp[kg * 64];

    // precomputed ldmatrix addresses (loop-invariant)
    uint32_t addrR[8][2];
    {
        int lbase = (lane & 15) * 128 + ((lane >> 4) << 4);
#pragma unroll
        for (int kk = 0; kk < 8; kk++) {
            uint32_t kbase = myslot + (uint32_t)((kk >> 2) * 8192);
            uint32_t loff  = (uint32_t)SWZ(lbase + (kk & 3) * 32);
#pragma unroll
            for (int mt = 0; mt < 2; mt++)
                addrR[kk][mt] = kbase + (uint32_t)((mg * 2 + mt) * 2048) + loff;
        }
    }

    for (int l = 0; l < L_; l++) {
        int par = l & 1;
        size_t pb = (size_t)l * 3072 * 64;
        float ia = __ldg(&g_proj[pb + (size_t)j * 64 + b]);
        float ic = __ldg(&g_proj[pb + (size_t)(MEM + j) * 64 + b]);
        float io = __ldg(&g_proj[pb + (size_t)(2 * MEM + j) * 64 + b]);

        // JIT producer: mg0-lane0 of each kg polls its group, issues its chunk
        if (mg == 0 && lane == 0) {
            unsigned int tgt = 16u * (unsigned int)(l + 1);
            while (*mycnt < tgt) { }
            __threadfence();
            FENCE_ASYNC_ALL();
            MBAR_EXPECT_TX(myfull, 16384);
            TMA_LD(myslot,        &tmap, kg * 128,      par * 64, 0, myfull);
            TMA_LD(myslot + 8192, &tmap, kg * 128 + 64, par * 64, 0, myfull);
        }

        float acc[2][2][4];
#pragma unroll
        for (int a = 0; a < 2; a++)
#pragma unroll
            for (int b2 = 0; b2 < 2; b2++)
#pragma unroll
                for (int c = 0; c < 4; c++) acc[a][b2][c] = 0.0f;

        MBAR_WAIT(myfull, par);

#pragma unroll
        for (int kk = 0; kk < 8; kk++) {
#pragma unroll
            for (int mt = 0; mt < 2; mt++) {
                uint32_t a0, a1, a2, a3;
                ldmatrix4(a0, a1, a2, a3, addrR[kk][mt]);
                mma16816h(acc[mt][0], a0, a1, a2, a3, wreg[kk][0].x, wreg[kk][0].y);
                mma16816h(acc[mt][1], a0, a1, a2, a3, wreg[kk][1].x, wreg[kk][1].y);
            }
        }

        // RED: every kg writes its own buffer (no cross-warp ordering needed)
        {
            float* rp = RED + (size_t)kg * (64 * 17);
            int r0 = mg * 32 + (lane >> 2);
            int c0 = (lane & 3) * 2;
#pragma unroll
            for (int mt = 0; mt < 2; mt++)
#pragma unroll
                for (int np = 0; np < 2; np++) {
                    float* qp = rp + (r0 + mt * 16) * 17 + np * 8 + c0;
                    qp[0]          = acc[mt][np][0];
                    qp[1]          = acc[mt][np][1];
                    qp[8 * 17]     = acc[mt][np][2];
                    qp[8 * 17 + 1] = acc[mt][np][3];
                }
        }
        __syncthreads();

        // combine + nBRC update; write h to buffer (l+1)&1
        {
            float ma = 0.0f, mc = 0.0f;
#pragma unroll
            for (int qq = 0; qq < 8; qq++) {
                const float* rq = RED + (size_t)qq * (64 * 17);
                ma += rq[b * 17 + jj];
                mc += rq[b * 17 + 8 + jj];
            }
            float a  = 1.0f + tanh_acc(ia + ma);
            float cg = sigmoid_acc(ic + mc);
            float hn = cg * hreg + (1.0f - cg) * tanh_acc(io + a * hreg);
            hreg = hn;
            g_hA[(((l + 1) & 1) * 64 + b) * MEM + j] = __float2half(hn);
            g_mem[(size_t)l * (MEM * B_) + (size_t)j * B_ + b] = hn;
        }
        __syncthreads();

        if (t == 0) {
            __threadfence();
            atomicAdd(&g_grp[mygrp * 64], 1u);
        }
    }
}

// ---------------- K3: logits + softmax (4 timesteps/block) --------------------------
__global__ void __launch_bounds__(256) logits_kernel(const float* __restrict__ Wact,
                                                     const float* __restrict__ bact,
                                                     float* __restrict__ out) {
    __shared__ float Wa[MEM * DEC];
    int t = threadIdx.x;
    int l = blockIdx.x * 4 + (t >> 6);
    int b = t & 63;
    for (int idx = t; idx < MEM * DEC; idx += 256) Wa[idx] = Wact[idx];
    __syncthreads();

    float a0 = bact[0], a1 = bact[1], a2 = bact[2];
    const float* mp = g_mem + (size_t)l * MEM * B_ + b;
#pragma unroll 8
    for (int k = 0; k < MEM; k++) {
        float v = mp[(size_t)k * B_];
        a0 += v * Wa[k * 3 + 0];
        a1 += v * Wa[k * 3 + 1];
        a2 += v * Wa[k * 3 + 2];
    }
    float m  = fmaxf(a0, fmaxf(a1, a2));
    float e0 = __expf(a0 - m), e1 = __expf(a1 - m), e2 = __expf(a2 - m);
    float inv = 1.0f / (e0 + e1 + e2);
    size_t ob = ((size_t)b * L_ + l) * DEC;
    out[ob + 0] = e0 * inv;
    out[ob + 1] = e1 * inv;
    out[ob + 2] = e2 * inv;
}

// ---------------- launch --------------------------------------------------------------
typedef CUresult (*PFN_tmapEncode)(
    CUtensorMap*, CUtensorMapDataType, cuuint32_t, void*,
    const cuuint64_t*, const cuuint64_t*, const cuuint32_t*, const cuuint32_t*,
    CUtensorMapInterleave, CUtensorMapSwizzle, CUtensorMapL2promotion,
    CUtensorMapFloatOOBfill);

extern "C" void kernel_launch(void* const* d_in, const int* in_sizes, int n_in,
                              void* d_out, int out_size) {
    (void)in_sizes; (void)n_in; (void)out_size;
    const float* x   = (const float*)d_in[0];
    const float* Ws  = (const float*)d_in[1];
    const float* bs  = (const float*)d_in[2];
    const float* Wim = (const float*)d_in[3];
    const float* Wmm = (const float*)d_in[4];
    const float* Wac = (const float*)d_in[5];
    const float* bac = (const float*)d_in[6];
    float* out = (float*)d_out;

    void* hs_ptr = nullptr;
    cudaGetSymbolAddress(&hs_ptr, g_hA);
    PFN_tmapEncode enc = nullptr;
    cudaDriverEntryPointQueryResult qr;
    cudaGetDriverEntryPoint("cuTensorMapEncodeTiled", (void**)&enc,
                            cudaEnableDefault, &qr);
    CUtensorMap tmap;
    {
        cuuint64_t dims[3]    = {MEM, 128, 1};
        cuuint64_t strides[2] = {MEM * 2, (cuuint64_t)MEM * 2 * 128};
        cuuint32_t box[3]     = {64, 64, 1};
        cuuint32_t es[3]      = {1, 1, 1};
        enc(&tmap, CU_TENSOR_MAP_DATA_TYPE_FLOAT16, 3, hs_ptr,
            dims, strides, box, es,
            CU_TENSOR_MAP_INTERLEAVE_NONE, CU_TENSOR_MAP_SWIZZLE_128B,
            CU_TENSOR_MAP_L2_PROMOTION_L2_128B, CU_TENSOR_MAP_FLOAT_OOB_FILL_NONE);
    }

    cudaFuncSetAttribute(proj_tc,  cudaFuncAttributeMaxDynamicSharedMemorySize, PSM_TOT);
    cudaFuncSetAttribute(scan_tc,  cudaFuncAttributeMaxDynamicSharedMemorySize, SMEM_SCAN);

    reset_kernel<<<1, 512>>>();
    sense_kernel<<<B_ * L_ / 8, 128>>>(x, Ws, bs);
    wprep_kernel<<<24, 256>>>(Wim);
    proj_tc<<<dim3(24, 256), 256, PSM_TOT>>>();
    scan_tc<<<NCTA, NT, SMEM_SCAN>>>(Wmm, tmap);
    logits_kernel<<<L_ / 4, 256>>>(Wac, bac, out);
}